// round 2
// baseline (speedup 1.0000x reference)
#include <cuda_runtime.h>
#include <cstdint>
#include <cstddef>

// Problem constants
#define Bb   16
#define Nn   4096
#define Dd   256
#define Kk   512
#define ROWS (Bb * Nn)        // 65536
#define TM   128              // rows per block
#define TK   128              // codes per k-chunk
#define TD   64               // dims per d-chunk
#define ZP   130              // z smem pitch (rows dim): >=TM, ==2 mod 4 (8B-aligned LDS.64, 4-way max fill conflict)
#define CP2  264              // duplicated-cb smem pitch (floats): >=2*TK, mult of 4 (16B-aligned LDS.128)
#define NBLK (ROWS / TM)      // 512
#define THREADS 256

// Scratch device globals (no allocation allowed)
__device__ double g_loss;
__device__ int    g_mflag;             // bit0: packed bool bytes; bit1: float32 pattern
__device__ float  g_esq[Kk];
__device__ float  g_cbT[Dd * 2 * Kk];  // transposed + duplicated codebook: [d][2k],[2k+1] = cb[k][d]  (1MB)

__global__ void init_k() {
    g_loss  = 0.0;
    g_mflag = 0;
}

// Classify mask dtype from raw bytes (first ROWS/4 words are in-bounds for all candidate dtypes).
__global__ void detect_k(const unsigned int* __restrict__ m) {
    int i = blockIdx.x * blockDim.x + threadIdx.x;
    int flags = 0;
    for (int idx = i; idx < (ROWS / 4); idx += gridDim.x * blockDim.x) {
        unsigned int v = m[idx];
        if (v == 0x3F800000u) flags |= 2;      // float 1.0f
        else if (v > 1u)      flags |= 1;      // packed bool bytes
    }
    if (flags) atomicOr(&g_mflag, flags);
}

// Transpose + duplicate codebook into g_cbT (one-time, ~1MB, L2-resident afterwards).
__global__ void prep_cbT(const float* __restrict__ cb) {
    int k = blockIdx.x;        // 0..511
    int d = threadIdx.x;       // 0..255
    float v = cb[(size_t)k * Dd + d];
    g_cbT[(size_t)d * (2 * Kk) + 2 * k]     = v;
    g_cbT[(size_t)d * (2 * Kk) + 2 * k + 1] = v;
}

__global__ void esq_k(const float* __restrict__ cb) {
    int k = blockIdx.x * blockDim.x + threadIdx.x;
    if (k < Kk) {
        const float* p = cb + (size_t)k * Dd;
        float s = 0.f;
#pragma unroll 8
        for (int d = 0; d < Dd; ++d) s += p[d] * p[d];
        g_esq[k] = s;
    }
}

__device__ __forceinline__ int read_mask(const void* m, int n, int flag) {
    if (flag & 2) return ((const float*)m)[n] != 0.0f;
    if (flag & 1) return ((const unsigned char*)m)[n] != 0;
    return ((const int*)m)[n] != 0;
}

// Packed dual-FMA (Blackwell f32x2). a.lo += z.lo*c.lo; a.hi += z.hi*c.hi
__device__ __forceinline__ void ffma2(double& a, double z, double c) {
    asm("fma.rn.f32x2 %0, %1, %2, %0;" : "+d"(a) : "d"(z), "d"(c));
}
__device__ __forceinline__ float lo32(double a) { return __int_as_float(__double2loint(a)); }
__device__ __forceinline__ float hi32(double a) { return __int_as_float(__double2hiint(a)); }

// Main VQ kernel: CTA tile = 128 rows x all 512 codes (4 k-chunks of 128), D chunked by 64.
// 256 threads as 16x16: rg handles rows 8*rg..8*rg+7 (as 4 f32x2 pairs),
// cg handles codes 8*cg..8*cg+7 (duplicated pairs from g_cbT).
__global__ __launch_bounds__(THREADS, 2) void vq_main(
    const float* __restrict__ z,
    const void*  __restrict__ mask,
    const float* __restrict__ cb,
    float* __restrict__ out_q,
    float* __restrict__ out_i,
    int write_idx)
{
    extern __shared__ float sh[];
    float* zs  = sh;                  // [TD][ZP]   z chunk, d-major (row pairs contiguous)
    float* cbs = sh + TD * ZP;        // [TD][CP2]  duplicated cb chunk, d-major

    const int tid = threadIdx.x;
    const int rg  = tid >> 4;         // 0..15
    const int cg  = tid & 15;         // 0..15
    const int r0  = blockIdx.x * TM;
    const int mflag = g_mflag;

    const int fi0 = tid >> 4;         // z-fill: row start
    const int fd4 = tid & 15;         // z-fill: dim quad

    float bs[8];
    int   bk[8];
#pragma unroll
    for (int p = 0; p < 8; ++p) { bs[p] = 3.4e38f; bk[p] = 0; }

    for (int kc = 0; kc < Kk / TK; ++kc) {
        double acc[4][8];
#pragma unroll
        for (int rp = 0; rp < 4; ++rp)
#pragma unroll
            for (int c = 0; c < 8; ++c) acc[rp][c] = 0.0;

        for (int dc = 0; dc < Dd / TD; ++dc) {
            const int dbase = dc * TD;
            __syncthreads();

            // ---- fill z chunk (transpose from global): zs[d][i] ----
#pragma unroll
            for (int ii = fi0; ii < TM; ii += 16) {
                const float4 v = *reinterpret_cast<const float4*>(
                    &z[(size_t)(r0 + ii) * Dd + dbase + fd4 * 4]);
                zs[(fd4 * 4 + 0) * ZP + ii] = v.x;
                zs[(fd4 * 4 + 1) * ZP + ii] = v.y;
                zs[(fd4 * 4 + 2) * ZP + ii] = v.z;
                zs[(fd4 * 4 + 3) * ZP + ii] = v.w;
            }

            // ---- fill duplicated cb chunk (straight copy from g_cbT, conflict-free) ----
            {
                const size_t gbase = (size_t)dbase * (2 * Kk) + kc * (2 * TK);
#pragma unroll
                for (int it = 0; it < 16; ++it) {
                    int idx = tid + it * THREADS;         // 0..4095 float4s
                    int row = idx >> 6;                   // d within chunk
                    int c4  = idx & 63;                   // float4 within dup row
                    const float4 v = *reinterpret_cast<const float4*>(
                        &g_cbT[gbase + (size_t)row * (2 * Kk) + c4 * 4]);
                    *reinterpret_cast<float4*>(&cbs[row * CP2 + c4 * 4]) = v;
                }
            }
            __syncthreads();

            // ---- main FFMA2 loop ----
#pragma unroll 4
            for (int d = 0; d < TD; ++d) {
                const double* zp = reinterpret_cast<const double*>(&zs[d * ZP + 8 * rg]);
                double z2[4];
#pragma unroll
                for (int p = 0; p < 4; ++p) z2[p] = zp[p];

                const double2* cp = reinterpret_cast<const double2*>(&cbs[d * CP2 + 16 * cg]);
                double cd[8];
#pragma unroll
                for (int q = 0; q < 4; ++q) {
                    double2 t = cp[q];
                    cd[2 * q]     = t.x;
                    cd[2 * q + 1] = t.y;
                }
#pragma unroll
                for (int rp = 0; rp < 4; ++rp)
#pragma unroll
                    for (int c = 0; c < 8; ++c)
                        ffma2(acc[rp][c], z2[rp], cd[c]);
            }
        }

        // ---- fold k-chunk into running argmin (score = e_sq - 2*dot) ----
#pragma unroll
        for (int c = 0; c < 8; ++c) {
            const int k = kc * TK + 8 * cg + c;
            const float eq = g_esq[k];
#pragma unroll
            for (int rp = 0; rp < 4; ++rp) {
                float slo = fmaf(-2.f, lo32(acc[rp][c]), eq);
                float shi = fmaf(-2.f, hi32(acc[rp][c]), eq);
                if (slo < bs[2 * rp])     { bs[2 * rp]     = slo; bk[2 * rp]     = k; }
                if (shi < bs[2 * rp + 1]) { bs[2 * rp + 1] = shi; bk[2 * rp + 1] = k; }
            }
        }
    }

    // ---- cross-thread argmin reduction over the 16 cg lanes per row ----
    __syncthreads();
    float* rs    = cbs;                        // [TM][16] scores
    int*   ri    = (int*)(cbs + TM * 16);      // [TM][16] indices
    int*   bestk = (int*)(cbs + 2 * TM * 16);  // [TM]
#pragma unroll
    for (int p = 0; p < 8; ++p) {
        rs[(8 * rg + p) * 16 + cg] = bs[p];
        ri[(8 * rg + p) * 16 + cg] = bk[p];
    }
    __syncthreads();
    if (tid < TM) {
        float best = rs[tid * 16];
        int   kb   = ri[tid * 16];
        for (int j = 1; j < 16; ++j) {
            float v  = rs[tid * 16 + j];
            int   kv = ri[tid * 16 + j];
            if (v < best || (v == best && kv < kb)) { best = v; kb = kv; }
        }
        bestk[tid] = kb;
    }
    __syncthreads();

    // ---- epilogue: gather, straight-through quantize, mask, loss (thread = dim) ----
    float lsum = 0.f;
    for (int it = 0; it < TM; ++it) {
        int row = r0 + it;
        int k   = bestk[it];
        float zv = __ldg(&z[(size_t)row * Dd + tid]);
        float e  = __ldg(&cb[(size_t)k * Dd + tid]);
        float d1 = e - zv;
        float q  = zv + d1;
        float lq = q - zv;
        lsum = fmaf(lq, lq, lsum);
        int mk = read_mask(mask, row, mflag);
        out_q[(size_t)row * Dd + tid] = mk ? q : 0.f;
    }
    if (write_idx && tid < TM) {
        int row = r0 + tid;
        int mk  = read_mask(mask, row, mflag);
        out_i[row] = mk ? (float)bestk[tid] : -1.0f;
    }

    // ---- block-reduce loss, one atomic per block ----
#pragma unroll
    for (int off = 16; off > 0; off >>= 1)
        lsum += __shfl_down_sync(0xFFFFFFFFu, lsum, off);
    __syncthreads();
    float* wsum = rs;
    if ((tid & 31) == 0) wsum[tid >> 5] = lsum;
    __syncthreads();
    if (tid == 0) {
        float t = 0.f;
        for (int w = 0; w < 8; ++w) t += wsum[w];
        atomicAdd(&g_loss, (double)t);
    }
}

__global__ void fin_k(float* out_loss) {
    out_loss[0] = (float)(0.25 * g_loss / (double)((size_t)ROWS * Dd));
}

extern "C" void kernel_launch(void* const* d_in, const int* in_sizes, int n_in,
                              void* d_out, int out_size) {
    const float* z    = (const float*)d_in[0];
    const void*  mask = d_in[1];
    const float* cb   = (const float*)d_in[2];

    float* out   = (float*)d_out;
    float* out_q = out;
    float* out_i = out + (size_t)ROWS * Dd;
    float* out_l = out_i + ROWS;

    const int need_full = (out_size >= (int)((size_t)ROWS * Dd + ROWS + 1));
    const int smem = (TD * ZP + TD * CP2) * (int)sizeof(float);  // ~100.9 KB

    cudaFuncSetAttribute(vq_main, cudaFuncAttributeMaxDynamicSharedMemorySize, smem);

    init_k<<<1, 1>>>();
    detect_k<<<16, 256>>>((const unsigned int*)mask);
    prep_cbT<<<Kk, Dd>>>(cb);
    esq_k<<<2, 256>>>(cb);
    vq_main<<<NBLK, THREADS, smem>>>(z, mask, cb, out_q, out_i, need_full);
    if (need_full) fin_k<<<1, 1>>>(out_l);
}

// round 3
// speedup vs baseline: 1.0183x; 1.0183x over previous
#include <cuda_runtime.h>
#include <cstdint>
#include <cstddef>

// Problem constants
#define Bb   16
#define Nn   4096
#define Dd   256
#define Kk   512
#define ROWS (Bb * Nn)        // 65536
#define TM   128              // rows per block
#define TK   128              // codes per k-chunk
#define TD   64               // dims per d-chunk
#define ZP   130              // z smem pitch: ==2 mod 4 (8B-aligned LDS.64)
#define CP2  264              // duplicated-cb smem pitch (floats), mult of 4
#define NBLK (ROWS / TM)      // 512
#define THREADS 256

// Scratch device globals (no allocation allowed)
__device__ double g_loss;
__device__ int    g_mflag;             // bit0: packed bool bytes; bit1: float32 pattern
__device__ float  g_esq[Kk];
__device__ float  g_cbT[Dd * 2 * Kk];  // transposed + duplicated codebook (1MB, L2-resident)

__global__ void init_k() {
    g_loss  = 0.0;
    g_mflag = 0;
}

// Classify mask dtype from raw bytes (first ROWS/4 words in-bounds for all candidate dtypes).
__global__ void detect_k(const unsigned int* __restrict__ m) {
    int i = blockIdx.x * blockDim.x + threadIdx.x;
    int flags = 0;
    for (int idx = i; idx < (ROWS / 4); idx += gridDim.x * blockDim.x) {
        unsigned int v = m[idx];
        if (v == 0x3F800000u) flags |= 2;      // float 1.0f
        else if (v > 1u)      flags |= 1;      // packed bool bytes
    }
    if (flags) atomicOr(&g_mflag, flags);
}

// Transpose + duplicate codebook into g_cbT.
__global__ void prep_cbT(const float* __restrict__ cb) {
    int k = blockIdx.x;        // 0..511
    int d = threadIdx.x;       // 0..255
    float v = cb[(size_t)k * Dd + d];
    g_cbT[(size_t)d * (2 * Kk) + 2 * k]     = v;
    g_cbT[(size_t)d * (2 * Kk) + 2 * k + 1] = v;
}

// ||e_k||^2: one warp per code, lanes parallel over d. 64 blocks x 256 thr = 512 warps.
__global__ void esq_k(const float* __restrict__ cb) {
    int w    = (blockIdx.x * blockDim.x + threadIdx.x) >> 5;   // 0..511
    int lane = threadIdx.x & 31;
    const float* p = cb + (size_t)w * Dd;
    float s = 0.f;
#pragma unroll
    for (int j = 0; j < Dd / 32; ++j) {
        float v = p[lane + 32 * j];
        s = fmaf(v, v, s);
    }
#pragma unroll
    for (int off = 16; off > 0; off >>= 1)
        s += __shfl_down_sync(0xFFFFFFFFu, s, off);
    if (lane == 0) g_esq[w] = s;
}

__device__ __forceinline__ int read_mask(const void* m, int n, int flag) {
    if (flag & 2) return ((const float*)m)[n] != 0.0f;
    if (flag & 1) return ((const unsigned char*)m)[n] != 0;
    return ((const int*)m)[n] != 0;
}

// Packed dual-FMA (Blackwell f32x2). a.lo += z.lo*c.lo; a.hi += z.hi*c.hi
__device__ __forceinline__ void ffma2(double& a, double z, double c) {
    asm("fma.rn.f32x2 %0, %1, %2, %0;" : "+d"(a) : "d"(z), "d"(c));
}
__device__ __forceinline__ float lo32(double a) { return __int_as_float(__double2loint(a)); }
__device__ __forceinline__ float hi32(double a) { return __int_as_float(__double2hiint(a)); }

// Main VQ kernel: CTA tile = 128 rows x 512 codes (4 k-chunks), D chunked by 64.
// 256 threads as 16x16: rg -> rows 8*rg..8*rg+7 (4 f32x2 pairs), cg -> codes 8*cg..8*cg+7.
__global__ __launch_bounds__(THREADS, 2) void vq_main(
    const float* __restrict__ z,
    const void*  __restrict__ mask,
    const float* __restrict__ cb,
    float* __restrict__ out_q,
    float* __restrict__ out_i,
    int write_idx)
{
    extern __shared__ float sh[];
    float* zs  = sh;                  // [TD][ZP]   z chunk, d-major (row pairs contiguous)
    float* cbs = sh + TD * ZP;        // [TD][CP2]  duplicated cb chunk, d-major

    const int tid = threadIdx.x;
    const int rg  = tid >> 4;         // 0..15
    const int cg  = tid & 15;         // 0..15
    const int r0  = blockIdx.x * TM;
    const int mflag = g_mflag;

    const int fi0 = tid >> 4;         // z-fill: row start
    const int fd4 = tid & 15;         // z-fill: dim quad

    float bs[8];
    int   bk[8];
#pragma unroll
    for (int p = 0; p < 8; ++p) { bs[p] = 3.4e38f; bk[p] = 0; }

    for (int kc = 0; kc < Kk / TK; ++kc) {
        double acc[4][8];
#pragma unroll
        for (int rp = 0; rp < 4; ++rp)
#pragma unroll
            for (int c = 0; c < 8; ++c) acc[rp][c] = 0.0;

        for (int dc = 0; dc < Dd / TD; ++dc) {
            const int dbase = dc * TD;
            __syncthreads();

            // ---- fill z chunk (transpose from global): zs[d][i] ----
#pragma unroll
            for (int ii = fi0; ii < TM; ii += 16) {
                const float4 v = *reinterpret_cast<const float4*>(
                    &z[(size_t)(r0 + ii) * Dd + dbase + fd4 * 4]);
                zs[(fd4 * 4 + 0) * ZP + ii] = v.x;
                zs[(fd4 * 4 + 1) * ZP + ii] = v.y;
                zs[(fd4 * 4 + 2) * ZP + ii] = v.z;
                zs[(fd4 * 4 + 3) * ZP + ii] = v.w;
            }

            // ---- fill duplicated cb chunk (straight copy from g_cbT, conflict-free) ----
            {
                const size_t gbase = (size_t)dbase * (2 * Kk) + kc * (2 * TK);
#pragma unroll
                for (int it = 0; it < 16; ++it) {
                    int idx = tid + it * THREADS;         // 0..4095 float4s
                    int row = idx >> 6;                   // d within chunk
                    int c4  = idx & 63;                   // float4 within dup row
                    const float4 v = *reinterpret_cast<const float4*>(
                        &g_cbT[gbase + (size_t)row * (2 * Kk) + c4 * 4]);
                    *reinterpret_cast<float4*>(&cbs[row * CP2 + c4 * 4]) = v;
                }
            }
            __syncthreads();

            // ---- main FFMA2 loop (unroll 1: cap live operand regs, no spills) ----
#pragma unroll 1
            for (int d = 0; d < TD; ++d) {
                const double* zp = reinterpret_cast<const double*>(&zs[d * ZP + 8 * rg]);
                double z2[4];
#pragma unroll
                for (int p = 0; p < 4; ++p) z2[p] = zp[p];

                const double2* cp = reinterpret_cast<const double2*>(&cbs[d * CP2 + 16 * cg]);
                double cd[8];
#pragma unroll
                for (int q = 0; q < 4; ++q) {
                    double2 t = cp[q];
                    cd[2 * q]     = t.x;
                    cd[2 * q + 1] = t.y;
                }
#pragma unroll
                for (int rp = 0; rp < 4; ++rp)
#pragma unroll
                    for (int c = 0; c < 8; ++c)
                        ffma2(acc[rp][c], z2[rp], cd[c]);
            }
        }

        // ---- fold k-chunk into running argmin (score = e_sq - 2*dot) ----
#pragma unroll
        for (int c = 0; c < 8; ++c) {
            const int k = kc * TK + 8 * cg + c;
            const float eq = __ldg(&g_esq[k]);
#pragma unroll
            for (int rp = 0; rp < 4; ++rp) {
                float slo = fmaf(-2.f, lo32(acc[rp][c]), eq);
                float shi = fmaf(-2.f, hi32(acc[rp][c]), eq);
                if (slo < bs[2 * rp])     { bs[2 * rp]     = slo; bk[2 * rp]     = k; }
                if (shi < bs[2 * rp + 1]) { bs[2 * rp + 1] = shi; bk[2 * rp + 1] = k; }
            }
        }
    }

    // ---- cross-thread argmin reduction over the 16 cg lanes per row ----
    __syncthreads();
    float* rs    = cbs;                        // [TM][16] scores
    int*   ri    = (int*)(cbs + TM * 16);      // [TM][16] indices
    int*   bestk = (int*)(cbs + 2 * TM * 16);  // [TM]
#pragma unroll
    for (int p = 0; p < 8; ++p) {
        rs[(8 * rg + p) * 16 + cg] = bs[p];
        ri[(8 * rg + p) * 16 + cg] = bk[p];
    }
    __syncthreads();
    if (tid < TM) {
        float best = rs[tid * 16];
        int   kb   = ri[tid * 16];
        for (int j = 1; j < 16; ++j) {
            float v  = rs[tid * 16 + j];
            int   kv = ri[tid * 16 + j];
            if (v < best || (v == best && kv < kb)) { best = v; kb = kv; }
        }
        bestk[tid] = kb;
    }
    __syncthreads();

    // ---- epilogue: gather, straight-through quantize, mask, loss (thread = dim) ----
    float lsum = 0.f;
    for (int it = 0; it < TM; ++it) {
        int row = r0 + it;
        int k   = bestk[it];
        float zv = __ldg(&z[(size_t)row * Dd + tid]);
        float e  = __ldg(&cb[(size_t)k * Dd + tid]);
        float d1 = e - zv;
        float q  = zv + d1;
        float lq = q - zv;
        lsum = fmaf(lq, lq, lsum);
        int mk = read_mask(mask, row, mflag);
        out_q[(size_t)row * Dd + tid] = mk ? q : 0.f;
    }
    if (write_idx && tid < TM) {
        int row = r0 + tid;
        int mk  = read_mask(mask, row, mflag);
        out_i[row] = mk ? (float)bestk[tid] : -1.0f;
    }

    // ---- block-reduce loss, one atomic per block ----
#pragma unroll
    for (int off = 16; off > 0; off >>= 1)
        lsum += __shfl_down_sync(0xFFFFFFFFu, lsum, off);
    __syncthreads();
    float* wsum = rs;
    if ((tid & 31) == 0) wsum[tid >> 5] = lsum;
    __syncthreads();
    if (tid == 0) {
        float t = 0.f;
        for (int w = 0; w < 8; ++w) t += wsum[w];
        atomicAdd(&g_loss, (double)t);
    }
}

__global__ void fin_k(float* out_loss) {
    out_loss[0] = (float)(0.25 * g_loss / (double)((size_t)ROWS * Dd));
}

extern "C" void kernel_launch(void* const* d_in, const int* in_sizes, int n_in,
                              void* d_out, int out_size) {
    const float* z    = (const float*)d_in[0];
    const void*  mask = d_in[1];
    const float* cb   = (const float*)d_in[2];

    float* out   = (float*)d_out;
    float* out_q = out;
    float* out_i = out + (size_t)ROWS * Dd;
    float* out_l = out_i + ROWS;

    const int need_full = (out_size >= (int)((size_t)ROWS * Dd + ROWS + 1));
    const int smem = (TD * ZP + TD * CP2) * (int)sizeof(float);  // ~100.9 KB

    cudaFuncSetAttribute(vq_main, cudaFuncAttributeMaxDynamicSharedMemorySize, smem);

    init_k<<<1, 1>>>();
    detect_k<<<16, 256>>>((const unsigned int*)mask);
    prep_cbT<<<Kk, Dd>>>(cb);
    esq_k<<<64, 256>>>(cb);
    vq_main<<<NBLK, THREADS, smem>>>(z, mask, cb, out_q, out_i, need_full);
    if (need_full) fin_k<<<1, 1>>>(out_l);
}

// round 4
// speedup vs baseline: 2.0691x; 2.0320x over previous
#include <cuda_runtime.h>
#include <cstdint>
#include <cstddef>

// Problem constants
#define Bb   16
#define Nn   4096
#define Dd   256
#define Kk   512
#define ROWS (Bb * Nn)        // 65536
#define TM   128              // rows per CTA
#define TK   128              // codes per k-chunk
#define TD   64               // dims per d-chunk
#define TDP  68               // zs pitch (floats): TD+4, mult of 4 (float4 fill alignment)
#define CP   132              // cbs pitch (floats): TK+4, mult of 4
#define NBLK (ROWS / TM)      // 512
#define THREADS 256

// Scratch device globals (no allocation allowed)
__device__ double g_loss;
__device__ int    g_mflag;            // bit0: packed bool bytes; bit1: float32 pattern
__device__ float  g_esq[Kk];
__device__ float  g_cbT[Dd * Kk];     // transposed codebook: cbT[d][k]  (512KB, L2-resident)

__global__ void init_k() {
    g_loss  = 0.0;
    g_mflag = 0;
}

// Classify mask dtype from raw bytes (first ROWS/4 words in-bounds for all candidate dtypes).
__global__ void detect_k(const unsigned int* __restrict__ m) {
    int i = blockIdx.x * blockDim.x + threadIdx.x;
    int flags = 0;
    for (int idx = i; idx < (ROWS / 4); idx += gridDim.x * blockDim.x) {
        unsigned int v = m[idx];
        if (v == 0x3F800000u) flags |= 2;      // float 1.0f
        else if (v > 1u)      flags |= 1;      // packed bool bytes
    }
    if (flags) atomicOr(&g_mflag, flags);
}

// Tiled transpose cb[K][D] -> cbT[D][K]. 32x32 tiles, smem padded, coalesced both sides.
__global__ void prep_cbT(const float* __restrict__ cb) {
    __shared__ float t[32][33];
    const int kt = blockIdx.x * 32;       // code tile base (16 tiles)
    const int dt = blockIdx.y * 32;       // dim tile base  (8 tiles)
    const int x  = threadIdx.x;           // 0..31
    const int y0 = threadIdx.y;           // 0..7
#pragma unroll
    for (int y = y0; y < 32; y += 8)
        t[y][x] = cb[(size_t)(kt + y) * Dd + dt + x];
    __syncthreads();
#pragma unroll
    for (int y = y0; y < 32; y += 8)
        g_cbT[(size_t)(dt + y) * Kk + kt + x] = t[x][y];
}

// ||e_k||^2: one warp per code.
__global__ void esq_k(const float* __restrict__ cb) {
    int w    = (blockIdx.x * blockDim.x + threadIdx.x) >> 5;   // 0..511
    int lane = threadIdx.x & 31;
    const float* p = cb + (size_t)w * Dd;
    float s = 0.f;
#pragma unroll
    for (int j = 0; j < Dd / 32; ++j) {
        float v = p[lane + 32 * j];
        s = fmaf(v, v, s);
    }
#pragma unroll
    for (int off = 16; off > 0; off >>= 1)
        s += __shfl_down_sync(0xFFFFFFFFu, s, off);
    if (lane == 0) g_esq[w] = s;
}

__device__ __forceinline__ int read_mask(const void* m, int n, int flag) {
    if (flag & 2) return ((const float*)m)[n] != 0.0f;
    if (flag & 1) return ((const unsigned char*)m)[n] != 0;
    return ((const int*)m)[n] != 0;
}

// Main VQ kernel: CTA tile = 128 rows x 512 codes (4 k-chunks), D chunked by 64.
// 256 threads as 16x16: rg -> rows 8*rg..8*rg+7, cg -> codes 8*cg..8*cg+7.
__global__ __launch_bounds__(THREADS, 2) void vq_main(
    const float* __restrict__ z,
    const void*  __restrict__ mask,
    const float* __restrict__ cb,
    float* __restrict__ out_q,
    float* __restrict__ out_i,
    int write_idx)
{
    extern __shared__ float sh[];
    float* zs  = sh;                  // [TM][TDP]  z chunk, row-major
    float* cbs = sh + TM * TDP;       // [TD][CP]   cb chunk, d-major (codes contiguous)

    const int tid = threadIdx.x;
    const int rg  = tid >> 4;         // 0..15
    const int cg  = tid & 15;         // 0..15
    const int r0  = blockIdx.x * TM;
    const int mflag = g_mflag;

    float bs[8];
    int   bk[8];
#pragma unroll
    for (int p = 0; p < 8; ++p) { bs[p] = 3.4e38f; bk[p] = 0; }

    const int zrow0 = 8 * rg;         // this thread's first row (local)
    const int ccol0 = 8 * cg;         // this thread's first code (within chunk)

    for (int kc = 0; kc < Kk / TK; ++kc) {
        float acc[8][8];
#pragma unroll
        for (int r = 0; r < 8; ++r)
#pragma unroll
            for (int c = 0; c < 8; ++c) acc[r][c] = 0.f;

        for (int dc = 0; dc < Dd / TD; ++dc) {
            const int dbase = dc * TD;
            __syncthreads();

            // ---- fill z chunk, row-major (coalesced float4 both sides) ----
#pragma unroll
            for (int it = 0; it < 8; ++it) {
                int idx  = tid + it * THREADS;     // 0..2047 float4s
                int row  = idx >> 4;               // 0..127
                int quad = idx & 15;               // 0..15
                const float4 v = *reinterpret_cast<const float4*>(
                    &z[(size_t)(r0 + row) * Dd + dbase + quad * 4]);
                *reinterpret_cast<float4*>(&zs[row * TDP + quad * 4]) = v;
            }
            // ---- fill cb chunk from cbT (straight copy, conflict-free) ----
#pragma unroll
            for (int it = 0; it < 8; ++it) {
                int idx = tid + it * THREADS;      // 0..2047 float4s
                int row = idx >> 5;                // d within chunk 0..63
                int q   = idx & 31;                // float4 within row
                const float4 v = *reinterpret_cast<const float4*>(
                    &g_cbT[(size_t)(dbase + row) * Kk + kc * TK + q * 4]);
                *reinterpret_cast<float4*>(&cbs[row * CP + q * 4]) = v;
            }
            __syncthreads();

            // ---- main FMA loop: 8x8 outer product per d ----
#pragma unroll 1
            for (int d = 0; d < TD; ++d) {
                float zr[8];
#pragma unroll
                for (int r = 0; r < 8; ++r)
                    zr[r] = zs[(zrow0 + r) * TDP + d];

                const float4 c0 = *reinterpret_cast<const float4*>(&cbs[d * CP + ccol0]);
                const float4 c1 = *reinterpret_cast<const float4*>(&cbs[d * CP + ccol0 + 4]);
                float cc[8] = {c0.x, c0.y, c0.z, c0.w, c1.x, c1.y, c1.z, c1.w};

#pragma unroll
                for (int r = 0; r < 8; ++r)
#pragma unroll
                    for (int c = 0; c < 8; ++c)
                        acc[r][c] = fmaf(zr[r], cc[c], acc[r][c]);
            }
        }

        // ---- fold k-chunk into running argmin (score = e_sq - 2*dot) ----
#pragma unroll
        for (int c = 0; c < 8; ++c) {
            const int k = kc * TK + ccol0 + c;
            const float eq = __ldg(&g_esq[k]);
#pragma unroll
            for (int r = 0; r < 8; ++r) {
                float s = fmaf(-2.f, acc[r][c], eq);
                if (s < bs[r]) { bs[r] = s; bk[r] = k; }
            }
        }
    }

    // ---- cross-thread argmin reduction over the 16 cg lanes per row ----
    __syncthreads();
    float* rs    = cbs;                        // [TM][16] scores
    int*   ri    = (int*)(cbs + TM * 16);      // [TM][16] indices
    int*   bestk = (int*)(cbs + 2 * TM * 16);  // [TM]
#pragma unroll
    for (int r = 0; r < 8; ++r) {
        rs[(zrow0 + r) * 16 + cg] = bs[r];
        ri[(zrow0 + r) * 16 + cg] = bk[r];
    }
    __syncthreads();
    if (tid < TM) {
        float best = rs[tid * 16];
        int   kb   = ri[tid * 16];
        for (int j = 1; j < 16; ++j) {
            float v  = rs[tid * 16 + j];
            int   kv = ri[tid * 16 + j];
            if (v < best || (v == best && kv < kb)) { best = v; kb = kv; }
        }
        bestk[tid] = kb;
    }
    __syncthreads();

    // ---- epilogue: gather, straight-through quantize, mask, loss (thread = dim) ----
    float lsum = 0.f;
    for (int it = 0; it < TM; ++it) {
        int row = r0 + it;
        int k   = bestk[it];
        float zv = __ldg(&z[(size_t)row * Dd + tid]);
        float e  = __ldg(&cb[(size_t)k * Dd + tid]);
        float d1 = e - zv;
        float q  = zv + d1;
        float lq = q - zv;
        lsum = fmaf(lq, lq, lsum);
        int mk = read_mask(mask, row, mflag);
        out_q[(size_t)row * Dd + tid] = mk ? q : 0.f;
    }
    if (write_idx && tid < TM) {
        int row = r0 + tid;
        int mk  = read_mask(mask, row, mflag);
        out_i[row] = mk ? (float)bestk[tid] : -1.0f;
    }

    // ---- block-reduce loss, one atomic per block ----
#pragma unroll
    for (int off = 16; off > 0; off >>= 1)
        lsum += __shfl_down_sync(0xFFFFFFFFu, lsum, off);
    __syncthreads();
    float* wsum = rs;
    if ((tid & 31) == 0) wsum[tid >> 5] = lsum;
    __syncthreads();
    if (tid == 0) {
        float t = 0.f;
        for (int w = 0; w < 8; ++w) t += wsum[w];
        atomicAdd(&g_loss, (double)t);
    }
}

__global__ void fin_k(float* out_loss) {
    out_loss[0] = (float)(0.25 * g_loss / (double)((size_t)ROWS * Dd));
}

extern "C" void kernel_launch(void* const* d_in, const int* in_sizes, int n_in,
                              void* d_out, int out_size) {
    const float* z    = (const float*)d_in[0];
    const void*  mask = d_in[1];
    const float* cb   = (const float*)d_in[2];

    float* out   = (float*)d_out;
    float* out_q = out;
    float* out_i = out + (size_t)ROWS * Dd;
    float* out_l = out_i + ROWS;

    const int need_full = (out_size >= (int)((size_t)ROWS * Dd + ROWS + 1));
    const int smem = (TM * TDP + TD * CP) * (int)sizeof(float);  // ~67.8 KB

    cudaFuncSetAttribute(vq_main, cudaFuncAttributeMaxDynamicSharedMemorySize, smem);

    init_k<<<1, 1>>>();
    detect_k<<<16, 256>>>((const unsigned int*)mask);
    {
        dim3 g(Kk / 32, Dd / 32);
        dim3 b(32, 8);
        prep_cbT<<<g, b>>>(cb);
    }
    esq_k<<<64, 256>>>(cb);
    vq_main<<<NBLK, THREADS, smem>>>(z, mask, cb, out_q, out_i, need_full);
    if (need_full) fin_k<<<1, 1>>>(out_l);
}

// round 6
// speedup vs baseline: 2.4861x; 1.2016x over previous
#include <cuda_runtime.h>
#include <cuda_bf16.h>
#include <cstdint>
#include <cstddef>

// Problem constants
#define Bb   16
#define Nn   4096
#define Dd   256
#define Kk   512
#define ROWS (Bb * Nn)        // 65536
#define TMm  128              // rows per MMA CTA
#define NBLK (ROWS / TMm)     // 512
#define DELTA 0.05f

// smem layout (bytes): A-hi 4x16KB tiles, A-lo, B-hi chunk, B-lo chunk, esq, reduce
#define OFF_AH  0
#define OFF_AL  (64 * 1024)
#define OFF_BH  (128 * 1024)
#define OFF_BL  (144 * 1024)
#define OFF_ESQ (160 * 1024)   // 512 floats
#define OFF_RB1 (162 * 1024)   // float sb1[128][2]
#define OFF_RK1 (163 * 1024)   // int   sk1[128][2]
#define OFF_RB2 (164 * 1024)   // float sb2[128][2]
#define SMEM_SZ (165 * 1024)

// ---------------- device globals (scratch; no allocations allowed) ----------------
__device__ double g_loss;
__device__ int    g_mflag;
__device__ int    g_nflag;
__device__ float  g_esq[Kk];
__device__ int    g_bestk[ROWS];
__device__ int    g_flaglist[ROWS];
__device__ uint4  g_cbh4[Kk * Dd / 8];   // codebook hi bf16 [code][dim/8] (256KB)
__device__ uint4  g_cbl4[Kk * Dd / 8];   // codebook lo bf16 (256KB)

// ---------------- helpers ----------------
__device__ __forceinline__ uint32_t smem_u32(const void* p) {
    uint32_t a;
    asm("{ .reg .u64 t; cvta.to.shared.u64 t, %1; cvt.u32.u64 %0, t; }" : "=r"(a) : "l"(p));
    return a;
}

#define LDSM4(r, addr)                                                              \
    asm volatile("ldmatrix.sync.aligned.m8n8.x4.shared.b16 {%0,%1,%2,%3}, [%4];"    \
        : "=r"((r)[0]), "=r"((r)[1]), "=r"((r)[2]), "=r"((r)[3]) : "r"(addr))

#define MMA16816(c, a, b0, b1)                                                      \
    asm volatile("mma.sync.aligned.m16n8k16.row.col.f32.bf16.bf16.f32 "             \
        "{%0,%1,%2,%3}, {%4,%5,%6,%7}, {%8,%9}, {%0,%1,%2,%3};"                     \
        : "+f"((c)[0]), "+f"((c)[1]), "+f"((c)[2]), "+f"((c)[3])                    \
        : "r"((a)[0]), "r"((a)[1]), "r"((a)[2]), "r"((a)[3]), "r"(b0), "r"(b1))

// bf16 split-pack: 8 floats -> hi uint4 + lo uint4
__device__ __forceinline__ void split8(const float* v, uint4& h, uint4& l) {
    uint32_t hw[4], lw[4];
#pragma unroll
    for (int j = 0; j < 4; ++j) {
        __nv_bfloat16 h0 = __float2bfloat16(v[2 * j]);
        __nv_bfloat16 h1 = __float2bfloat16(v[2 * j + 1]);
        float l0 = v[2 * j]     - __bfloat162float(h0);
        float l1 = v[2 * j + 1] - __bfloat162float(h1);
        __nv_bfloat16 g0 = __float2bfloat16(l0);
        __nv_bfloat16 g1 = __float2bfloat16(l1);
        hw[j] = ((uint32_t)__bfloat16_as_ushort(h1) << 16) | __bfloat16_as_ushort(h0);
        lw[j] = ((uint32_t)__bfloat16_as_ushort(g1) << 16) | __bfloat16_as_ushort(g0);
    }
    h = make_uint4(hw[0], hw[1], hw[2], hw[3]);
    l = make_uint4(lw[0], lw[1], lw[2], lw[3]);
}

// merge (b1,k1,b2) with (ob1,ok1,ob2); argmin tie-break = lowest index
__device__ __forceinline__ void merge2(float& b1, int& k1, float& b2,
                                       float ob1, int ok1, float ob2) {
    float lose;
    if (ob1 < b1 || (ob1 == b1 && ok1 < k1)) { lose = b1; b1 = ob1; k1 = ok1; }
    else lose = ob1;
    b2 = fminf(b2, fminf(ob2, lose));
}

// ---------------- prologue kernels ----------------
__global__ void init_k() { g_loss = 0.0; g_mflag = 0; g_nflag = 0; }

__global__ void detect_k(const unsigned int* __restrict__ m) {
    int i = blockIdx.x * blockDim.x + threadIdx.x;
    int flags = 0;
    for (int idx = i; idx < (ROWS / 4); idx += gridDim.x * blockDim.x) {
        unsigned int v = m[idx];
        if (v == 0x3F800000u) flags |= 2;
        else if (v > 1u)      flags |= 1;
    }
    if (flags) atomicOr(&g_mflag, flags);
}

__global__ void prep_cbhl(const float* __restrict__ cb) {
    int code = blockIdx.x;
    int t    = threadIdx.x;         // 0..31, 8 dims each
    float v[8];
    const float* p = cb + (size_t)code * Dd + t * 8;
#pragma unroll
    for (int j = 0; j < 8; ++j) v[j] = p[j];
    uint4 h, l;
    split8(v, h, l);
    g_cbh4[code * 32 + t] = h;
    g_cbl4[code * 32 + t] = l;
}

__global__ void esq_k(const float* __restrict__ cb) {
    int w    = (blockIdx.x * blockDim.x + threadIdx.x) >> 5;
    int lane = threadIdx.x & 31;
    const float* p = cb + (size_t)w * Dd;
    float s = 0.f;
#pragma unroll
    for (int j = 0; j < Dd / 32; ++j) { float v = p[lane + 32 * j]; s = fmaf(v, v, s); }
#pragma unroll
    for (int off = 16; off > 0; off >>= 1) s += __shfl_down_sync(0xFFFFFFFFu, s, off);
    if (lane == 0) g_esq[w] = s;
}

__device__ __forceinline__ int read_mask(const void* m, int n, int flag) {
    if (flag & 2) return ((const float*)m)[n] != 0.0f;
    if (flag & 1) return ((const unsigned char*)m)[n] != 0;
    return ((const int*)m)[n] != 0;
}

// ---------------- main MMA kernel ----------------
// CTA: 128 rows x 512 codes (4 chunks of 128), K=256 (4 d-chunks of 64).
// 8 warps in 4(m) x 2(n) grid; warp tile 32 rows x 64 codes; mma.m16n8k16 bf16.
__global__ __launch_bounds__(256, 1) void vq_mma(const float* __restrict__ z) {
    extern __shared__ char smem[];
    const uint32_t sb = smem_u32(smem);
    const int tid  = threadIdx.x;
    const int lane = tid & 31;
    const int wid  = tid >> 5;
    const int wm   = wid >> 1;         // 0..3
    const int wn   = wid & 1;          // 0..1
    const int g    = lane >> 2;        // 0..7
    const int tg   = lane & 3;         // 0..3
    const int r0   = blockIdx.x * TMm;

    float* esq_s = (float*)(smem + OFF_ESQ);

    // ---- fill A (z hi/lo) once: 4 d-chunk tiles of [128 rows][64 dims] SW128 ----
#pragma unroll 4
    for (int it = 0; it < 16; ++it) {
        int idx = tid + it * 256;          // 0..4095
        int row = idx >> 5;                // 0..127
        int u   = idx & 31;                // uint4-chunk within row (8 dims)
        int dc  = u >> 3;
        int q   = u & 7;
        float v[8];
        const float* p = z + (size_t)(r0 + row) * Dd + u * 8;
        const float4 v0 = *reinterpret_cast<const float4*>(p);
        const float4 v1 = *reinterpret_cast<const float4*>(p + 4);
        v[0] = v0.x; v[1] = v0.y; v[2] = v0.z; v[3] = v0.w;
        v[4] = v1.x; v[5] = v1.y; v[6] = v1.z; v[7] = v1.w;
        uint4 h, l;
        split8(v, h, l);
        uint32_t off = dc * 16384 + row * 128 + ((q * 16) ^ ((row & 7) * 16));
        *reinterpret_cast<uint4*>(smem + OFF_AH + off) = h;
        *reinterpret_cast<uint4*>(smem + OFF_AL + off) = l;
    }
    esq_s[tid]       = g_esq[tid];
    esq_s[tid + 256] = g_esq[tid + 256];

    // ldmatrix per-lane constants
    const int sw      = (lane & 7) * 16;                       // swizzle xor (row&7 == lane&7)
    const int aRowT   = ((lane >> 3) & 1) * 8 + (lane & 7);    // row within 16-row tile
    const int aByteT  = (lane >> 4) * 16;                      // k-byte half
    const int bCodeT  = (lane >> 4) * 8 + (lane & 7);          // code within 16-code pair
    const int bByteT  = ((lane >> 3) & 1) * 16;

    // per-thread running best/second-best for 4 rows
    float bs1[4], bs2[4];
    int   bk1[4];
#pragma unroll
    for (int s = 0; s < 4; ++s) { bs1[s] = 3.4e38f; bs2[s] = 3.4e38f; bk1[s] = 0; }

    for (int kc = 0; kc < 4; ++kc) {               // code chunks of 128
        float acc[2][8][4];
#pragma unroll
        for (int mt = 0; mt < 2; ++mt)
#pragma unroll
            for (int nt = 0; nt < 8; ++nt)
#pragma unroll
                for (int c = 0; c < 4; ++c) acc[mt][nt][c] = 0.f;

        for (int dc = 0; dc < 4; ++dc) {           // d chunks of 64
            __syncthreads();
            // ---- fill B chunk hi/lo: [128 codes][64 dims] SW128 ----
#pragma unroll
            for (int it = 0; it < 4; ++it) {
                int idx  = tid + it * 256;         // 0..1023
                int code = idx >> 3;
                int q    = idx & 7;
                int gi   = (kc * 128 + code) * 32 + dc * 8 + q;
                uint32_t off = code * 128 + ((q * 16) ^ ((code & 7) * 16));
                *reinterpret_cast<uint4*>(smem + OFF_BH + off) = g_cbh4[gi];
                *reinterpret_cast<uint4*>(smem + OFF_BL + off) = g_cbl4[gi];
            }
            __syncthreads();

            const uint32_t aBase = sb + OFF_AH + dc * 16384 +
                                   (uint32_t)((wm * 32 + aRowT) * 128);
            const uint32_t bBase = sb + OFF_BH + (uint32_t)((wn * 64 + bCodeT) * 128);

#pragma unroll
            for (int ks = 0; ks < 4; ++ks) {       // K16 steps
                const uint32_t xa = (uint32_t)((ks * 32 + aByteT) ^ sw);
                const uint32_t xb = (uint32_t)((ks * 32 + bByteT) ^ sw);

                uint32_t ah[2][4], al[2][4];
#pragma unroll
                for (int mt = 0; mt < 2; ++mt) {
                    LDSM4(ah[mt], aBase + mt * (16 * 128) + xa);
                    LDSM4(al[mt], aBase + (OFF_AL - OFF_AH) + mt * (16 * 128) + xa);
                }
                uint32_t bh[4][4], bl[4][4];
#pragma unroll
                for (int np = 0; np < 4; ++np) {
                    LDSM4(bh[np], bBase + np * (16 * 128) + xb);
                    LDSM4(bl[np], bBase + (OFF_BL - OFF_BH) + np * (16 * 128) + xb);
                }
#pragma unroll
                for (int mt = 0; mt < 2; ++mt)
#pragma unroll
                    for (int np = 0; np < 4; ++np) {
                        MMA16816(acc[mt][2 * np],     ah[mt], bh[np][0], bh[np][1]); // hh even
                        MMA16816(acc[mt][2 * np],     ah[mt], bl[np][0], bl[np][1]); // hl
                        MMA16816(acc[mt][2 * np],     al[mt], bh[np][0], bh[np][1]); // lh
                        MMA16816(acc[mt][2 * np + 1], ah[mt], bh[np][2], bh[np][3]); // hh odd
                        MMA16816(acc[mt][2 * np + 1], ah[mt], bl[np][2], bl[np][3]);
                        MMA16816(acc[mt][2 * np + 1], al[mt], bh[np][2], bh[np][3]);
                    }
            }
        }

        // ---- fold chunk into running argmin: score = esq - 2*dot ----
        const int ccbase = kc * 128 + wn * 64;
#pragma unroll
        for (int mt = 0; mt < 2; ++mt)
#pragma unroll
            for (int nt = 0; nt < 8; ++nt)
#pragma unroll
                for (int c = 0; c < 4; ++c) {
                    int code = ccbase + nt * 8 + 2 * tg + (c & 1);
                    int slot = mt * 2 + (c >> 1);
                    float s = fmaf(-2.f, acc[mt][nt][c], esq_s[code]);
                    if (s < bs1[slot]) { bs2[slot] = bs1[slot]; bs1[slot] = s; bk1[slot] = code; }
                    else if (s < bs2[slot]) bs2[slot] = s;
                }
    }

    // ---- quad reduce (lanes sharing a row: tg 0..3) ----
#pragma unroll
    for (int s = 0; s < 4; ++s) {
#pragma unroll
        for (int m = 1; m <= 2; m <<= 1) {
            float ob1 = __shfl_xor_sync(0xFFFFFFFFu, bs1[s], m);
            int   ok1 = __shfl_xor_sync(0xFFFFFFFFu, bk1[s], m);
            float ob2 = __shfl_xor_sync(0xFFFFFFFFu, bs2[s], m);
            merge2(bs1[s], bk1[s], bs2[s], ob1, ok1, ob2);
        }
    }
    __syncthreads();
    float* sb1 = (float*)(smem + OFF_RB1);
    int*   sk1 = (int*)  (smem + OFF_RK1);
    float* sb2 = (float*)(smem + OFF_RB2);
    if (tg == 0) {
#pragma unroll
        for (int s = 0; s < 4; ++s) {
            int row = wm * 32 + (s >> 1) * 16 + (s & 1) * 8 + g;
            sb1[row * 2 + wn] = bs1[s];
            sk1[row * 2 + wn] = bk1[s];
            sb2[row * 2 + wn] = bs2[s];
        }
    }
    __syncthreads();
    if (tid < TMm) {
        float b1 = sb1[tid * 2], b2 = sb2[tid * 2];
        int   k1 = sk1[tid * 2];
        merge2(b1, k1, b2, sb1[tid * 2 + 1], sk1[tid * 2 + 1], sb2[tid * 2 + 1]);
        int row = r0 + tid;
        g_bestk[row] = k1;
        if (b2 - b1 < DELTA) {
            int p = atomicAdd(&g_nflag, 1);
            g_flaglist[p] = row;
        }
    }
}

// ---------------- exact fp32 rescue for near-tie rows ----------------
__global__ __launch_bounds__(256) void vq_exact(const float* __restrict__ z,
                                                const float* __restrict__ cb) {
    const int nf   = g_nflag;
    const int gw   = (blockIdx.x * blockDim.x + threadIdx.x) >> 5;
    const int lane = threadIdx.x & 31;
    const int nw   = (gridDim.x * blockDim.x) >> 5;
    for (int i = gw; i < nf; i += nw) {
        const int row = g_flaglist[i];
        float zr[8];
#pragma unroll
        for (int j = 0; j < 8; ++j) zr[j] = z[(size_t)row * Dd + j * 32 + lane];
        float best = 3.4e38f; int bk = 0;
        for (int k = 0; k < Kk; ++k) {
            const float* ck = cb + (size_t)k * Dd;
            float p = 0.f;
#pragma unroll
            for (int j = 0; j < 8; ++j) p = fmaf(zr[j], ck[j * 32 + lane], p);
#pragma unroll
            for (int off = 16; off > 0; off >>= 1) p += __shfl_xor_sync(0xFFFFFFFFu, p, off);
            float s = fmaf(-2.f, p, g_esq[k]);
            if (s < best) { best = s; bk = k; }
        }
        if (lane == 0) g_bestk[row] = bk;
    }
}

// ---------------- epilogue: gather, quantize, mask, loss ----------------
__global__ __launch_bounds__(256) void epi_k(const float* __restrict__ z,
                                             const void*  __restrict__ mask,
                                             const float* __restrict__ cb,
                                             float* __restrict__ out_q,
                                             float* __restrict__ out_i,
                                             int write_idx) {
    const int tid = threadIdx.x;
    const int r0  = blockIdx.x * TMm;
    const int mflag = g_mflag;
    float lsum = 0.f;
    for (int it = 0; it < TMm; ++it) {
        int row = r0 + it;
        int k   = g_bestk[row];
        float zv = __ldg(&z[(size_t)row * Dd + tid]);
        float e  = __ldg(&cb[(size_t)k * Dd + tid]);
        float d1 = e - zv;
        float q  = zv + d1;
        float lq = q - zv;
        lsum = fmaf(lq, lq, lsum);
        int mk = read_mask(mask, row, mflag);
        out_q[(size_t)row * Dd + tid] = mk ? q : 0.f;
    }
    if (write_idx && tid < TMm) {
        int row = r0 + tid;
        int mk  = read_mask(mask, row, mflag);
        out_i[row] = mk ? (float)g_bestk[row] : -1.0f;
    }
#pragma unroll
    for (int off = 16; off > 0; off >>= 1)
        lsum += __shfl_down_sync(0xFFFFFFFFu, lsum, off);
    __shared__ float wsum[8];
    if ((tid & 31) == 0) wsum[tid >> 5] = lsum;
    __syncthreads();
    if (tid == 0) {
        float t = 0.f;
        for (int w = 0; w < 8; ++w) t += wsum[w];
        atomicAdd(&g_loss, (double)t);
    }
}

__global__ void fin_k(float* out_loss) {
    out_loss[0] = (float)(0.25 * g_loss / (double)((size_t)ROWS * Dd));
}

// ---------------- launch ----------------
extern "C" void kernel_launch(void* const* d_in, const int* in_sizes, int n_in,
                              void* d_out, int out_size) {
    const float* z    = (const float*)d_in[0];
    const void*  mask = d_in[1];
    const float* cb   = (const float*)d_in[2];

    float* out   = (float*)d_out;
    float* out_q = out;
    float* out_i = out + (size_t)ROWS * Dd;
    float* out_l = out_i + ROWS;

    const int need_full = (out_size >= (int)((size_t)ROWS * Dd + ROWS + 1));

    cudaFuncSetAttribute(vq_mma, cudaFuncAttributeMaxDynamicSharedMemorySize, SMEM_SZ);

    init_k<<<1, 1>>>();
    detect_k<<<16, 256>>>((const unsigned int*)mask);
    prep_cbhl<<<Kk, 32>>>(cb);
    esq_k<<<64, 256>>>(cb);
    vq_mma<<<NBLK, 256, SMEM_SZ>>>(z);
    vq_exact<<<128, 256>>>(z, cb);
    epi_k<<<NBLK, 256>>>(z, mask, cb, out_q, out_i, need_full);
    if (need_full) fin_k<<<1, 1>>>(out_l);
}